// round 10
// baseline (speedup 1.0000x reference)
#include <cuda_runtime.h>
#include <cuda_fp16.h>
#include <cstdint>

#define B_DIM 1024
#define L_DIM 200
#define C_DIM 384
#define OUT_D 10000
#define M1    (B_DIM * L_DIM)     // 204800

#define SROW  392                 // smem row stride in halves (784 B, 16B-aligned,
                                  // 196 banks/row -> conflict-free ldmatrix)

// ---- device scratch (static allocations only) ------------------------------
__device__ __half g_h[(size_t)M1 * C_DIM];          // 157 MB fp16 h
__device__ float  g_cv[B_DIM * C_DIM];              // pooled code vectors
__device__ __half g_wfc[C_DIM * C_DIM];             // W_fc in fp16
__device__ __half g_wout[(size_t)OUT_D * C_DIM];    // W_out in fp16
__device__ float  g_spart[3 * (size_t)M1];          // per-n-block score partials

// ---- helpers ---------------------------------------------------------------
__device__ __forceinline__ void ldsm4(uint32_t (&r)[4], uint32_t saddr) {
    asm volatile("ldmatrix.sync.aligned.m8n8.x4.shared.b16 {%0,%1,%2,%3}, [%4];\n"
                 : "=r"(r[0]), "=r"(r[1]), "=r"(r[2]), "=r"(r[3]) : "r"(saddr));
}

__device__ __forceinline__ void mma16816(float (&c)[4], const uint32_t (&a)[4],
                                         uint32_t b0, uint32_t b1) {
    asm volatile(
        "mma.sync.aligned.m16n8k16.row.col.f32.f16.f16.f32 "
        "{%0,%1,%2,%3}, {%4,%5,%6,%7}, {%8,%9}, {%0,%1,%2,%3};\n"
        : "+f"(c[0]), "+f"(c[1]), "+f"(c[2]), "+f"(c[3])
        : "r"(a[0]), "r"(a[1]), "r"(a[2]), "r"(a[3]), "r"(b0), "r"(b1));
}

// tanh: inputs have |x| ~ 0.02 (std); polynomial exact to ~1e-9 for |x|<=0.25,
// accurate tanhf fallback for the (never-in-practice) tail.
__device__ __forceinline__ float tanh_fast(float x) {
    float x2 = x * x;
    float p = fmaf(x2, fmaf(x2, 0.133333333f, -0.333333333f), 1.0f);
    float v = x * p;
    if (fabsf(x) > 0.25f) v = tanhf(x);
    return v;
}

__global__ __launch_bounds__(256)
void f2h_kernel(const float* __restrict__ s, __half* __restrict__ d, int n4) {
    int i = blockIdx.x * blockDim.x + threadIdx.x;
    if (i < n4) {
        float4 f = reinterpret_cast<const float4*>(s)[i];
        __half2 h0 = __floats2half2_rn(f.x, f.y);
        __half2 h1 = __floats2half2_rn(f.z, f.w);
        __half2* dp = reinterpret_cast<__half2*>(d) + 2 * i;
        dp[0] = h0; dp[1] = h1;
    }
}

// ============================================================================
// Single-shot full-K HMMA GEMM. CTA tile 128x128, K=384 fully staged in smem
// (A 98 KB + B 98 KB), ONE barrier, then 24 uninterrupted k-slices of MMAs.
//   GATHER=1 (GEMM1): A rows gathered fp32->fp16 from embedding tables;
//                     epilogue: tanh, fp16 h store, fused score partials.
//   GATHER=0 (GEMM2): A = dense fp32 (cv); epilogue: +bias, fp32 out, n guard.
// 8 warps as 4(m) x 2(n); warp tile 32x64.
// ============================================================================
template <int GATHER>
__global__ __launch_bounds__(256)
void ss_gemm(const float* __restrict__ Adense,
             const int* __restrict__ starts, const int* __restrict__ paths,
             const int* __restrict__ ends,
             const float* __restrict__ node_emb, const float* __restrict__ path_emb,
             const __half* __restrict__ Bw, const float* __restrict__ bias,
             const float* __restrict__ a_vec,
             void* __restrict__ Cout, int Nw) {
    extern __shared__ __align__(16) __half smem_buf[];
    __half* sA = smem_buf;                 // 128 x SROW halves
    __half* sB = smem_buf + 128 * SROW;    // 128 x SROW halves
    __shared__ float sAvec[128];
    __shared__ float sScore[2][128];

    const int tid = threadIdx.x;
    const int m0 = blockIdx.y * 128, n0 = blockIdx.x * 128;

    if (GATHER && tid < 128) sAvec[tid] = a_vec[n0 + tid];

    // -------- stage A and B (full K=384), 2 threads per row, 192 halves each
    {
        const int row = tid >> 1;
        const int seg = (tid & 1) * 192;
        const int m = m0 + row;
        int i_s = 0, i_p = 0, i_e = 0;
        if (GATHER) { i_s = starts[m]; i_p = paths[m]; i_e = ends[m]; }
        const int nr = n0 + row;
        const bool bvalid = (nr < Nw);

        #pragma unroll
        for (int q = 0; q < 24; q++) {
            const int k = seg + q * 8;
            // ---- A: 8 fp32 -> 8 fp16
            const float* ap;
            if (GATHER) {
                if (k < 128)      ap = node_emb + (size_t)i_s * 128 + k;
                else if (k < 256) ap = path_emb + (size_t)i_p * 128 + (k - 128);
                else              ap = node_emb + (size_t)i_e * 128 + (k - 256);
            } else {
                ap = Adense + (size_t)m * C_DIM + k;
            }
            float4 f0 = reinterpret_cast<const float4*>(ap)[0];
            float4 f1 = reinterpret_cast<const float4*>(ap)[1];
            __half2 h0 = __floats2half2_rn(f0.x, f0.y);
            __half2 h1 = __floats2half2_rn(f0.z, f0.w);
            __half2 h2 = __floats2half2_rn(f1.x, f1.y);
            __half2 h3 = __floats2half2_rn(f1.z, f1.w);
            *reinterpret_cast<uint4*>(&sA[row * SROW + k]) =
                make_uint4(*(uint32_t*)&h0, *(uint32_t*)&h1,
                           *(uint32_t*)&h2, *(uint32_t*)&h3);
            // ---- B: 8 fp16 copy (zero-fill past Nw)
            uint4 ub = make_uint4(0, 0, 0, 0);
            if (bvalid)
                ub = *reinterpret_cast<const uint4*>(Bw + (size_t)nr * C_DIM + k);
            *reinterpret_cast<uint4*>(&sB[row * SROW + k]) = ub;
        }
    }
    __syncthreads();

    // -------- compute: 24 k-slices, no barriers
    const int lane = tid & 31, warp = tid >> 5;
    const int wm = warp & 3, wn = warp >> 2;
    const int g = lane >> 2, t4 = lane & 3;
    const int a_row = (lane & 7) + ((lane >> 3) & 1) * 8;
    const int a_ko  = (lane >> 4) * 8;
    const int b_row = (lane & 7) + ((lane >> 4) & 1) * 8;
    const int b_ko  = ((lane >> 3) & 1) * 8;

    float acc[2][8][4];
    #pragma unroll
    for (int i = 0; i < 2; i++)
        #pragma unroll
        for (int j = 0; j < 8; j++)
            #pragma unroll
            for (int q = 0; q < 4; q++) acc[i][j][q] = 0.f;

    const uint32_t sa_base = (uint32_t)__cvta_generic_to_shared(sA);
    const uint32_t sb_base = (uint32_t)__cvta_generic_to_shared(sB);

    #pragma unroll 4
    for (int s = 0; s < 24; s++) {
        const int k0 = s * 16;
        uint32_t af[2][4], bf[4][4];
        #pragma unroll
        for (int i = 0; i < 2; i++)
            ldsm4(af[i], sa_base +
                  ((wm * 32 + i * 16 + a_row) * SROW + k0 + a_ko) * 2);
        #pragma unroll
        for (int p = 0; p < 4; p++)
            ldsm4(bf[p], sb_base +
                  ((wn * 64 + p * 16 + b_row) * SROW + k0 + b_ko) * 2);
        #pragma unroll
        for (int i = 0; i < 2; i++)
            #pragma unroll
            for (int j = 0; j < 8; j++)
                mma16816(acc[i][j], af[i],
                         bf[j >> 1][(j & 1) * 2], bf[j >> 1][(j & 1) * 2 + 1]);
    }

    // -------- epilogue
    if (GATHER) {
        float sc[2][2] = {{0.f, 0.f}, {0.f, 0.f}};
        #pragma unroll
        for (int i = 0; i < 2; i++) {
            #pragma unroll
            for (int j = 0; j < 8; j++) {
                const int r = m0 + wm * 32 + i * 16 + g;
                const int cl = wn * 64 + j * 8 + t4 * 2;
                const int c = n0 + cl;
                __half* C = (__half*)Cout;
                float v0 = tanh_fast(acc[i][j][0]);
                float v1 = tanh_fast(acc[i][j][1]);
                float v2 = tanh_fast(acc[i][j][2]);
                float v3 = tanh_fast(acc[i][j][3]);
                float a0 = sAvec[cl], a1 = sAvec[cl + 1];
                sc[i][0] = fmaf(v0, a0, fmaf(v1, a1, sc[i][0]));
                sc[i][1] = fmaf(v2, a0, fmaf(v3, a1, sc[i][1]));
                *reinterpret_cast<__half2*>(&C[(size_t)r * Nw + c]) =
                    __floats2half2_rn(v0, v1);
                *reinterpret_cast<__half2*>(&C[(size_t)(r + 8) * Nw + c]) =
                    __floats2half2_rn(v2, v3);
            }
        }
        // reduce score partials over the quad (4 lanes share a row-pair)
        #pragma unroll
        for (int i = 0; i < 2; i++)
            #pragma unroll
            for (int rh = 0; rh < 2; rh++) {
                sc[i][rh] += __shfl_xor_sync(0xffffffffu, sc[i][rh], 1);
                sc[i][rh] += __shfl_xor_sync(0xffffffffu, sc[i][rh], 2);
            }
        if (t4 == 0) {
            #pragma unroll
            for (int i = 0; i < 2; i++)
                #pragma unroll
                for (int rh = 0; rh < 2; rh++)
                    sScore[wn][wm * 32 + i * 16 + g + rh * 8] = sc[i][rh];
        }
        __syncthreads();
        if (tid < 128)
            g_spart[(size_t)blockIdx.x * M1 + m0 + tid] =
                sScore[0][tid] + sScore[1][tid];
    } else {
        float* C = (float*)Cout;
        #pragma unroll
        for (int i = 0; i < 2; i++) {
            #pragma unroll
            for (int j = 0; j < 8; j++) {
                const int r = m0 + wm * 32 + i * 16 + g;
                const int c = n0 + wn * 64 + j * 8 + t4 * 2;
                if (c < Nw)     C[(size_t)r * Nw + c]           = acc[i][j][0] + bias[c];
                if (c + 1 < Nw) C[(size_t)r * Nw + c + 1]       = acc[i][j][1] + bias[c + 1];
                if (c < Nw)     C[(size_t)(r + 8) * Nw + c]     = acc[i][j][2] + bias[c];
                if (c + 1 < Nw) C[(size_t)(r + 8) * Nw + c + 1] = acc[i][j][3] + bias[c + 1];
            }
        }
    }
}

// ============================================================================
// Attention: sum 3 score partials, softmax over L, single streaming h pass.
// ============================================================================
__global__ __launch_bounds__(256)
void attn_kernel(void) {
    __shared__ float s_w[L_DIM];
    __shared__ float red[8];
    const int b = blockIdx.x, tid = threadIdx.x;
    const int lane = tid & 31, warp = tid >> 5;

    float v = -1e30f;
    if (tid < L_DIM) {
        size_t m = (size_t)b * L_DIM + tid;
        v = g_spart[m] + g_spart[M1 + m] + g_spart[2 * (size_t)M1 + m];
    }
    float mx = v;
    #pragma unroll
    for (int o = 16; o; o >>= 1) mx = fmaxf(mx, __shfl_xor_sync(0xffffffffu, mx, o));
    if (lane == 0) red[warp] = mx;
    __syncthreads();
    if (tid == 0) {
        float t = red[0];
        #pragma unroll
        for (int i = 1; i < 8; i++) t = fmaxf(t, red[i]);
        red[0] = t;
    }
    __syncthreads();
    const float gmax = red[0];
    __syncthreads();
    float e = (tid < L_DIM) ? expf(v - gmax) : 0.f;
    float sm = e;
    #pragma unroll
    for (int o = 16; o; o >>= 1) sm += __shfl_xor_sync(0xffffffffu, sm, o);
    if (lane == 0) red[warp] = sm;
    __syncthreads();
    if (tid == 0) {
        float t = 0.f;
        #pragma unroll
        for (int i = 0; i < 8; i++) t += red[i];
        red[0] = t;
    }
    __syncthreads();
    const float inv = 1.0f / red[0];
    if (tid < L_DIM) s_w[tid] = e * inv;
    __syncthreads();

    if (tid < C_DIM / 2) {
        const __half2* hb2 = reinterpret_cast<const __half2*>(
            g_h + (size_t)b * L_DIM * C_DIM);
        float ax = 0.f, ay = 0.f;
        #pragma unroll 4
        for (int l = 0; l < L_DIM; l++) {
            float w = s_w[l];
            float2 f = __half22float2(hb2[l * (C_DIM / 2) + tid]);
            ax = fmaf(w, f.x, ax);
            ay = fmaf(w, f.y, ay);
        }
        *reinterpret_cast<float2*>(&g_cv[b * C_DIM + 2 * tid]) =
            make_float2(ax, ay);
    }
}

// ---------------------------------------------------------------------------
extern "C" void kernel_launch(void* const* d_in, const int* in_sizes, int n_in,
                              void* d_out, int out_size) {
    const int*   starts   = (const int*)  d_in[0];
    const int*   paths    = (const int*)  d_in[1];
    const int*   ends     = (const int*)  d_in[2];
    const float* node_emb = (const float*)d_in[3];
    const float* path_emb = (const float*)d_in[4];
    const float* W_fc     = (const float*)d_in[5];
    const float* a_vec    = (const float*)d_in[6];
    const float* W_out    = (const float*)d_in[7];
    const float* b_out    = (const float*)d_in[8];

    __half *p_h, *p_wfc, *p_wout;
    float  *p_cv;
    cudaGetSymbolAddress((void**)&p_h,    g_h);
    cudaGetSymbolAddress((void**)&p_cv,   g_cv);
    cudaGetSymbolAddress((void**)&p_wfc,  g_wfc);
    cudaGetSymbolAddress((void**)&p_wout, g_wout);

    const int dyn = 2 * 128 * SROW * (int)sizeof(__half);   // 200704 B

    // 0) weight conversions to fp16
    f2h_kernel<<<(C_DIM * C_DIM / 4 + 255) / 256, 256>>>(W_fc, p_wfc, C_DIM * C_DIM / 4);
    f2h_kernel<<<(OUT_D * C_DIM / 4 + 255) / 256, 256>>>(W_out, p_wout, OUT_D * C_DIM / 4);

    // 1) h = tanh(gather(ctx) @ W_fc^T) -> fp16, plus fused score partials
    cudaFuncSetAttribute(ss_gemm<1>, cudaFuncAttributeMaxDynamicSharedMemorySize, dyn);
    ss_gemm<1><<<dim3(3, M1 / 128), 256, dyn>>>(
        nullptr, starts, paths, ends, node_emb, path_emb,
        p_wfc, nullptr, a_vec, (void*)p_h, C_DIM);

    // 2) softmax + attention pooling -> cv fp32 [1024 x 384]
    attn_kernel<<<B_DIM, 256>>>();

    // 3) out = cv @ W_out^T + b_out -> fp32 [1024 x 10000]
    cudaFuncSetAttribute(ss_gemm<0>, cudaFuncAttributeMaxDynamicSharedMemorySize, dyn);
    ss_gemm<0><<<dim3((OUT_D + 127) / 128, B_DIM / 128), 256, dyn>>>(
        p_cv, nullptr, nullptr, nullptr, nullptr, nullptr,
        p_wout, b_out, nullptr, d_out, OUT_D);
}

// round 14
// speedup vs baseline: 1.9585x; 1.9585x over previous
#include <cuda_runtime.h>
#include <cuda_fp16.h>
#include <cstdint>

#define B_DIM 1024
#define L_DIM 200
#define C_DIM 384
#define OUT_D 10000
#define M1    (B_DIM * L_DIM)     // 204800

#define KT  32                    // k-tile
#define LDSX 40                   // smem row stride in halves (conflict-free)

// ---- device scratch (static allocations only) ------------------------------
__device__ __half g_h[(size_t)M1 * C_DIM];          // 157 MB fp16 h
__device__ float  g_cv[B_DIM * C_DIM];              // pooled code vectors
__device__ __half g_wfc[C_DIM * C_DIM];             // W_fc in fp16
__device__ __half g_wout[(size_t)OUT_D * C_DIM];    // W_out in fp16
__device__ float  g_spart[3 * (size_t)M1];          // per-n-block score partials

// ---- helpers ---------------------------------------------------------------
__device__ __forceinline__ void ldsm4(uint32_t (&r)[4], uint32_t saddr) {
    asm volatile("ldmatrix.sync.aligned.m8n8.x4.shared.b16 {%0,%1,%2,%3}, [%4];\n"
                 : "=r"(r[0]), "=r"(r[1]), "=r"(r[2]), "=r"(r[3]) : "r"(saddr));
}

__device__ __forceinline__ void mma16816(float (&c)[4], const uint32_t (&a)[4],
                                         uint32_t b0, uint32_t b1) {
    asm volatile(
        "mma.sync.aligned.m16n8k16.row.col.f32.f16.f16.f32 "
        "{%0,%1,%2,%3}, {%4,%5,%6,%7}, {%8,%9}, {%0,%1,%2,%3};\n"
        : "+f"(c[0]), "+f"(c[1]), "+f"(c[2]), "+f"(c[3])
        : "r"(a[0]), "r"(a[1]), "r"(a[2]), "r"(a[3]), "r"(b0), "r"(b1));
}

// tanh: inputs have |x| ~ 0.02 (std); polynomial exact to ~1e-9 for |x|<=0.25,
// accurate tanhf fallback for the (never-in-practice) tail.
__device__ __forceinline__ float tanh_fast(float x) {
    float x2 = x * x;
    float p = fmaf(x2, fmaf(x2, 0.133333333f, -0.333333333f), 1.0f);
    float v = x * p;
    if (fabsf(x) > 0.25f) v = tanhf(x);
    return v;
}

// ---- fp32 -> fp16 weight conversion ---------------------------------------
__global__ __launch_bounds__(256)
void f2h_kernel(const float* __restrict__ s, __half* __restrict__ d, int n4) {
    int i = blockIdx.x * blockDim.x + threadIdx.x;
    if (i < n4) {
        float4 f = reinterpret_cast<const float4*>(s)[i];
        __half2 h0 = __floats2half2_rn(f.x, f.y);
        __half2 h1 = __floats2half2_rn(f.z, f.w);
        __half2* dp = reinterpret_cast<__half2*>(d) + 2 * i;
        dp[0] = h0; dp[1] = h1;
    }
}

// ---------------------------------------------------------------------------
// Tensor-core GEMM: C[m,n] = op( sum_k A[m,k] * Bw16[n,k] )
//   GATHER=1: A rows gathered from embedding tables; TANH=1 also computes
//             per-n-block partial attention scores sum_c tanh(v)*a[c]
//             into g_spart[nb][m]  (deterministic, no atomics).
//   GATHER=0: A = Adense fp32; TANH=0 adds bias, fp32 out, n<Nw guard.
// CTA tile 128x128, k-tile 32, 8 warps as 4(m) x 2(n), warp tile 32x64.
// __launch_bounds__(256,2) pins regs <= 128 so 2 CTAs/SM residency holds.
// ---------------------------------------------------------------------------
template <int GATHER, int TANH>
__global__ __launch_bounds__(256, 2)
void mma_gemm(const float* __restrict__ Adense,
              const int* __restrict__ starts, const int* __restrict__ paths,
              const int* __restrict__ ends,
              const float* __restrict__ node_emb, const float* __restrict__ path_emb,
              const __half* __restrict__ Bw, const float* __restrict__ bias,
              const float* __restrict__ a_vec,
              void* __restrict__ Cout, int Nw) {
    __shared__ __align__(16) __half sA[2][128 * LDSX];
    __shared__ __align__(16) __half sB[2][128 * LDSX];
    __shared__ float sAvec[128];
    __shared__ float sScore[2][128];
    const int tid = threadIdx.x;
    const int m0 = blockIdx.y * 128, n0 = blockIdx.x * 128;

    // -------- loader mapping (256 thr: 2 threads per row, 16 halves each)
    const int ar = tid >> 1, aseg = (tid & 1) * 16;
    const int br = ar,       bseg = aseg;
    int i_s = 0, i_p = 0, i_e = 0;
    if (GATHER) { int m = m0 + ar; i_s = starts[m]; i_p = paths[m]; i_e = ends[m]; }

    float4 fA[4];
    uint4  uB[2];

    auto loadA = [&](int k0) {
        const float* ap;
        if (GATHER) {
            int k = k0 + aseg;
            if (k < 128)      ap = node_emb + (size_t)i_s * 128 + k;
            else if (k < 256) ap = path_emb + (size_t)i_p * 128 + (k - 128);
            else              ap = node_emb + (size_t)i_e * 128 + (k - 256);
        } else {
            ap = Adense + (size_t)(m0 + ar) * C_DIM + k0 + aseg;
        }
        #pragma unroll
        for (int q = 0; q < 4; q++) fA[q] = reinterpret_cast<const float4*>(ap)[q];
    };
    auto loadB = [&](int k0) {
        int nr = n0 + br;
        if (nr < Nw) {
            const uint4* bp = reinterpret_cast<const uint4*>(
                Bw + (size_t)nr * C_DIM + k0 + bseg);
            uB[0] = bp[0]; uB[1] = bp[1];
        } else {
            uB[0] = make_uint4(0, 0, 0, 0); uB[1] = make_uint4(0, 0, 0, 0);
        }
    };
    auto storeStage = [&](int buf) {
        __half2 h[8];
        #pragma unroll
        for (int q = 0; q < 4; q++) {
            h[2 * q]     = __floats2half2_rn(fA[q].x, fA[q].y);
            h[2 * q + 1] = __floats2half2_rn(fA[q].z, fA[q].w);
        }
        uint4 ua0 = make_uint4(*(uint32_t*)&h[0], *(uint32_t*)&h[1],
                               *(uint32_t*)&h[2], *(uint32_t*)&h[3]);
        uint4 ua1 = make_uint4(*(uint32_t*)&h[4], *(uint32_t*)&h[5],
                               *(uint32_t*)&h[6], *(uint32_t*)&h[7]);
        uint4* pa = reinterpret_cast<uint4*>(&sA[buf][ar * LDSX + aseg]);
        pa[0] = ua0; pa[1] = ua1;
        uint4* pb = reinterpret_cast<uint4*>(&sB[buf][br * LDSX + bseg]);
        pb[0] = uB[0]; pb[1] = uB[1];
    };

    // -------- compute mapping
    const int lane = tid & 31, warp = tid >> 5;
    const int wm = warp & 3, wn = warp >> 2;       // 4 x 2 warp grid
    const int g = lane >> 2, t4 = lane & 3;
    const int a_row = (lane & 7) + ((lane >> 3) & 1) * 8;
    const int a_ko  = (lane >> 4) * 8;
    const int b_row = (lane & 7) + ((lane >> 4) & 1) * 8;
    const int b_ko  = ((lane >> 3) & 1) * 8;

    float acc[2][8][4];
    #pragma unroll
    for (int i = 0; i < 2; i++)
        #pragma unroll
        for (int j = 0; j < 8; j++)
            #pragma unroll
            for (int q = 0; q < 4; q++) acc[i][j][q] = 0.f;

    if (TANH && tid < 128) sAvec[tid] = a_vec[n0 + tid];

    loadA(0); loadB(0); storeStage(0);
    __syncthreads();

    const int KSTEPS = C_DIM / KT;   // 12
    for (int s = 0; s < KSTEPS; ++s) {
        const int buf = s & 1;
        if (s + 1 < KSTEPS) { loadA((s + 1) * KT); loadB((s + 1) * KT); }

        #pragma unroll
        for (int ks = 0; ks < 2; ++ks) {
            const int ko = ks * 16;
            uint32_t af[2][4], bf[4][4];
            #pragma unroll
            for (int i = 0; i < 2; i++) {
                uint32_t ad = (uint32_t)__cvta_generic_to_shared(
                    &sA[buf][(wm * 32 + i * 16 + a_row) * LDSX + ko + a_ko]);
                ldsm4(af[i], ad);
            }
            #pragma unroll
            for (int p = 0; p < 4; p++) {
                uint32_t bd = (uint32_t)__cvta_generic_to_shared(
                    &sB[buf][(wn * 64 + p * 16 + b_row) * LDSX + ko + b_ko]);
                ldsm4(bf[p], bd);
            }
            #pragma unroll
            for (int i = 0; i < 2; i++)
                #pragma unroll
                for (int j = 0; j < 8; j++)
                    mma16816(acc[i][j], af[i],
                             bf[j >> 1][(j & 1) * 2], bf[j >> 1][(j & 1) * 2 + 1]);
        }
        if (s + 1 < KSTEPS) storeStage(buf ^ 1);
        __syncthreads();
    }

    // -------- epilogue
    float sc[2][2] = {{0.f, 0.f}, {0.f, 0.f}};   // score partials (i, row-half)
    #pragma unroll
    for (int i = 0; i < 2; i++) {
        #pragma unroll
        for (int j = 0; j < 8; j++) {
            const int r = m0 + wm * 32 + i * 16 + g;
            const int cl = wn * 64 + j * 8 + t4 * 2;   // col within block
            const int c = n0 + cl;
            if (TANH) {
                __half* C = (__half*)Cout;
                float v0 = tanh_fast(acc[i][j][0]);
                float v1 = tanh_fast(acc[i][j][1]);
                float v2 = tanh_fast(acc[i][j][2]);
                float v3 = tanh_fast(acc[i][j][3]);
                float a0 = sAvec[cl], a1 = sAvec[cl + 1];
                sc[i][0] = fmaf(v0, a0, fmaf(v1, a1, sc[i][0]));
                sc[i][1] = fmaf(v2, a0, fmaf(v3, a1, sc[i][1]));
                *reinterpret_cast<__half2*>(&C[(size_t)r * Nw + c]) =
                    __floats2half2_rn(v0, v1);
                *reinterpret_cast<__half2*>(&C[(size_t)(r + 8) * Nw + c]) =
                    __floats2half2_rn(v2, v3);
            } else {
                float* C = (float*)Cout;
                if (c < Nw)     C[(size_t)r * Nw + c]           = acc[i][j][0] + bias[c];
                if (c + 1 < Nw) C[(size_t)r * Nw + c + 1]       = acc[i][j][1] + bias[c + 1];
                if (c < Nw)     C[(size_t)(r + 8) * Nw + c]     = acc[i][j][2] + bias[c];
                if (c + 1 < Nw) C[(size_t)(r + 8) * Nw + c + 1] = acc[i][j][3] + bias[c + 1];
            }
        }
    }

    if (TANH) {
        // reduce score partials over the 4 lanes of each quad (same row)
        #pragma unroll
        for (int i = 0; i < 2; i++)
            #pragma unroll
            for (int rh = 0; rh < 2; rh++) {
                sc[i][rh] += __shfl_xor_sync(0xffffffffu, sc[i][rh], 1);
                sc[i][rh] += __shfl_xor_sync(0xffffffffu, sc[i][rh], 2);
            }
        if (t4 == 0) {
            #pragma unroll
            for (int i = 0; i < 2; i++)
                #pragma unroll
                for (int rh = 0; rh < 2; rh++)
                    sScore[wn][wm * 32 + i * 16 + g + rh * 8] = sc[i][rh];
        }
        __syncthreads();
        if (tid < 128)
            g_spart[(size_t)blockIdx.x * M1 + m0 + tid] =
                sScore[0][tid] + sScore[1][tid];
    }
}

// ---------------------------------------------------------------------------
// Attention: sum 3 score partials, softmax over L, single streaming h pass.
// ---------------------------------------------------------------------------
__global__ __launch_bounds__(256)
void attn_kernel(void) {
    __shared__ float s_w[L_DIM];
    __shared__ float red[8];
    const int b = blockIdx.x, tid = threadIdx.x;
    const int lane = tid & 31, warp = tid >> 5;

    float v = -1e30f;
    if (tid < L_DIM) {
        size_t m = (size_t)b * L_DIM + tid;
        v = g_spart[m] + g_spart[M1 + m] + g_spart[2 * (size_t)M1 + m];
    }
    float mx = v;
    #pragma unroll
    for (int o = 16; o; o >>= 1) mx = fmaxf(mx, __shfl_xor_sync(0xffffffffu, mx, o));
    if (lane == 0) red[warp] = mx;
    __syncthreads();
    if (tid == 0) {
        float t = red[0];
        #pragma unroll
        for (int i = 1; i < 8; i++) t = fmaxf(t, red[i]);
        red[0] = t;
    }
    __syncthreads();
    const float gmax = red[0];
    __syncthreads();
    float e = (tid < L_DIM) ? expf(v - gmax) : 0.f;
    float sm = e;
    #pragma unroll
    for (int o = 16; o; o >>= 1) sm += __shfl_xor_sync(0xffffffffu, sm, o);
    if (lane == 0) red[warp] = sm;
    __syncthreads();
    if (tid == 0) {
        float t = 0.f;
        #pragma unroll
        for (int i = 0; i < 8; i++) t += red[i];
        red[0] = t;
    }
    __syncthreads();
    const float inv = 1.0f / red[0];
    if (tid < L_DIM) s_w[tid] = e * inv;
    __syncthreads();

    // single streaming pass: cv[b,c] = sum_l w[l] * h[b,l,c]
    if (tid < C_DIM / 2) {
        const __half2* hb2 = reinterpret_cast<const __half2*>(
            g_h + (size_t)b * L_DIM * C_DIM);
        float ax = 0.f, ay = 0.f;
        #pragma unroll 8
        for (int l = 0; l < L_DIM; l++) {
            float w = s_w[l];
            float2 f = __half22float2(hb2[l * (C_DIM / 2) + tid]);
            ax = fmaf(w, f.x, ax);
            ay = fmaf(w, f.y, ay);
        }
        *reinterpret_cast<float2*>(&g_cv[b * C_DIM + 2 * tid]) =
            make_float2(ax, ay);
    }
}

// ---------------------------------------------------------------------------
extern "C" void kernel_launch(void* const* d_in, const int* in_sizes, int n_in,
                              void* d_out, int out_size) {
    const int*   starts   = (const int*)  d_in[0];
    const int*   paths    = (const int*)  d_in[1];
    const int*   ends     = (const int*)  d_in[2];
    const float* node_emb = (const float*)d_in[3];
    const float* path_emb = (const float*)d_in[4];
    const float* W_fc     = (const float*)d_in[5];
    const float* a_vec    = (const float*)d_in[6];
    const float* W_out    = (const float*)d_in[7];
    const float* b_out    = (const float*)d_in[8];

    __half *p_h, *p_wfc, *p_wout;
    float  *p_cv;
    cudaGetSymbolAddress((void**)&p_h,    g_h);
    cudaGetSymbolAddress((void**)&p_cv,   g_cv);
    cudaGetSymbolAddress((void**)&p_wfc,  g_wfc);
    cudaGetSymbolAddress((void**)&p_wout, g_wout);

    // 0) weight conversions to fp16
    f2h_kernel<<<(C_DIM * C_DIM / 4 + 255) / 256, 256>>>(W_fc, p_wfc, C_DIM * C_DIM / 4);
    f2h_kernel<<<(OUT_D * C_DIM / 4 + 255) / 256, 256>>>(W_out, p_wout, OUT_D * C_DIM / 4);

    // 1) h = tanh(gather(ctx) @ W_fc^T) -> fp16, plus per-n-block score partials
    mma_gemm<1, 1><<<dim3(C_DIM / 128, M1 / 128), 256>>>(
        nullptr, starts, paths, ends, node_emb, path_emb,
        p_wfc, nullptr, a_vec, (void*)p_h, C_DIM);

    // 2) softmax + attention pooling -> cv fp32 [1024 x 384] (single h pass)
    attn_kernel<<<B_DIM, 256>>>();

    // 3) out = cv @ W_out^T + b_out -> fp32 [1024 x 10000]
    mma_gemm<0, 0><<<dim3((OUT_D + 127) / 128, B_DIM / 128), 256>>>(
        p_cv, nullptr, nullptr, nullptr, nullptr, nullptr,
        p_wout, b_out, nullptr, d_out, OUT_D);
}